// round 1
// baseline (speedup 1.0000x reference)
#include <cuda_runtime.h>

#define HW 16384

// ---------------- scratch (static device arrays; no runtime allocation) ----
__device__ float g_wraw[8 * 72 * HW];   // raw dynamic kernels before GN
__device__ float g_xv[8 * 64 * HW];     // value path (conv1x1 grouped)
__device__ float g_gnpart[512 * 16];    // per-tile partial sums/sumsq (8 groups x2)
__device__ float g_gnstat[64 * 2];      // per (b,gg): mean, rstd
__device__ float g_chansum[512];        // per (b,c) sum of out
__device__ float g_yscale[512];         // channel attention scale

__constant__ float c_gnw[72], c_gnb[72], c_wdu1[256], c_wdu2[256];

// ---------------- Pass A: key conv + e1 + e2 + xv + GN partials ------------
#define WK_OFF  0
#define WE1_OFF 4608
#define WE2_OFF (4608 + 2048)
#define BE2_OFF (4608 + 2048 + 1152)
#define WC1_OFF (4608 + 2048 + 1152 + 72)
#define XT_OFF  9936                    // aligned start of x tile
#define SMEMA   ((XT_OFF + 64 * 324) * 4)

__global__ void __launch_bounds__(256, 1) passA(
    const float* __restrict__ x, const float* __restrict__ wkey,
    const float* __restrict__ we1, const float* __restrict__ we2,
    const float* __restrict__ be2, const float* __restrict__ wc1)
{
    extern __shared__ float sm[];
    const int tid = threadIdx.x;

    // load weights into smem (LDS broadcast beats LDC floor)
    for (int i = tid; i < 4608; i += 256) sm[WK_OFF + i] = wkey[i];
    for (int i = tid; i < 2048; i += 256) sm[WE1_OFF + i] = we1[i];
    for (int i = tid; i < 1152; i += 256) sm[WE2_OFF + i] = we2[i];
    if (tid < 72) sm[BE2_OFF + tid] = be2[tid];
    for (int i = tid; i < 2048; i += 256) sm[WC1_OFF + i] = wc1[i];

    const int b = blockIdx.z;
    const int ty0 = blockIdx.y << 4, tx0 = blockIdx.x << 4;
    const float* xb = x + (size_t)b * 64 * HW;
    float* xt = sm + XT_OFF;

    // x tile with 1-px halo, zero padded: [64][18][18]
    for (int i = tid; i < 64 * 324; i += 256) {
        int c = i / 324; int r = i - c * 324;
        int yy = r / 18, xx = r - yy * 18;
        int gy = ty0 + yy - 1, gx = tx0 + xx - 1;
        float v = 0.f;
        if ((unsigned)gy < 128u && (unsigned)gx < 128u)
            v = __ldg(xb + (c << 14) + (gy << 7) + gx);
        xt[i] = v;
    }
    __syncthreads();

    const int lty = tid >> 4, ltx = tid & 15;
    const float* pb = xt + lty * 18 + ltx;

    float e1v[32];
    #pragma unroll
    for (int half = 0; half < 2; half++) {
        float acc[16];
        #pragma unroll
        for (int o = 0; o < 16; o++) acc[o] = 0.f;

        for (int g = half * 4; g < half * 4 + 4; g++) {
            // cache 8-channel 3x3 patch in registers
            float p[72];
            #pragma unroll
            for (int ci = 0; ci < 8; ci++) {
                const float* pc = pb + (g * 8 + ci) * 324;
                #pragma unroll
                for (int dy = 0; dy < 3; dy++)
                    #pragma unroll
                    for (int dx = 0; dx < 3; dx++)
                        p[ci * 9 + dy * 3 + dx] = pc[dy * 18 + dx];
            }
            // grouped 3x3 key conv (+ReLU) for this group's 8 output channels
            float kk[8];
            #pragma unroll
            for (int oc = 0; oc < 8; oc++) {
                const float* w = sm + WK_OFF + (g * 8 + oc) * 72;
                float a = 0.f;
                #pragma unroll
                for (int t = 0; t < 72; t++) a = fmaf(p[t], w[t], a);
                kk[oc] = fmaxf(a, 0.f);
            }
            // e1 (grouped 1x1 over interleaved qk): accumulate contributions
            #pragma unroll
            for (int ci = 0; ci < 8; ci++) {
                float xc = p[ci * 9 + 4];
                float kv = kk[ci];
                int m = (g & 3) * 8 + ci;          // channel within 32-half
                const float* w1 = sm + WE1_OFF + half * 1024 + 2 * m;
                #pragma unroll
                for (int o = 0; o < 16; o++) {
                    acc[o] = fmaf(xc, w1[o * 64], acc[o]);
                    acc[o] = fmaf(kv, w1[o * 64 + 1], acc[o]);
                }
            }
        }
        #pragma unroll
        for (int o = 0; o < 16; o++) e1v[half * 16 + o] = fmaxf(acc[o], 0.f);
    }

    const int pix = ((ty0 + lty) << 7) + (tx0 + ltx);

    // e2 (grouped 1x1 + bias) -> w_raw; accumulate GN sums per group
    float lsum[8], lsq[8];
    #pragma unroll
    for (int gg = 0; gg < 8; gg++) {
        float s = 0.f, q = 0.f;
        const int grp = gg >> 2;
        for (int j = 0; j < 9; j++) {
            int o2 = gg * 9 + j;
            const float* w2 = sm + WE2_OFF + o2 * 16;
            float a = sm[BE2_OFF + o2];
            #pragma unroll
            for (int i = 0; i < 16; i++) a = fmaf(e1v[grp * 16 + i], w2[i], a);
            g_wraw[((b * 72 + o2) << 14) + pix] = a;
            s += a; q = fmaf(a, a, q);
        }
        lsum[gg] = s; lsq[gg] = q;
    }

    // xv = grouped conv1x1(x)
    #pragma unroll
    for (int grp = 0; grp < 2; grp++) {
        float xin[32];
        #pragma unroll
        for (int i = 0; i < 32; i++)
            xin[i] = xt[(grp * 32 + i) * 324 + (lty + 1) * 18 + (ltx + 1)];
        for (int oc = 0; oc < 32; oc++) {
            const float* w = sm + WC1_OFF + (grp * 32 + oc) * 32;
            float a = 0.f;
            #pragma unroll
            for (int i = 0; i < 32; i++) a = fmaf(xin[i], w[i], a);
            g_xv[((b * 64 + grp * 32 + oc) << 14) + pix] = a;
        }
    }

    // block-reduce GN partials (deterministic; no atomics)
    __syncthreads();
    #pragma unroll
    for (int off = 16; off; off >>= 1) {
        #pragma unroll
        for (int gg = 0; gg < 8; gg++) {
            lsum[gg] += __shfl_xor_sync(0xffffffffu, lsum[gg], off);
            lsq[gg]  += __shfl_xor_sync(0xffffffffu, lsq[gg], off);
        }
    }
    int wid = tid >> 5, lane = tid & 31;
    if (lane == 0) {
        #pragma unroll
        for (int gg = 0; gg < 8; gg++) {
            sm[wid * 16 + gg] = lsum[gg];
            sm[wid * 16 + 8 + gg] = lsq[gg];
        }
    }
    __syncthreads();
    if (tid < 16) {
        float s = 0.f;
        #pragma unroll
        for (int w = 0; w < 8; w++) s += sm[w * 16 + tid];
        int slot = (b << 6) + (blockIdx.y << 3) + blockIdx.x;
        g_gnpart[slot * 16 + tid] = s;
    }
}

// ---------------- GN stats finalize ----------------------------------------
__global__ void statsK()
{
    int t = threadIdx.x;               // t = b*8+gg
    if (t >= 64) return;
    int b = t >> 3, gg = t & 7;
    float s = 0.f, q = 0.f;
    for (int tile = 0; tile < 64; tile++) {
        s += g_gnpart[((b << 6) + tile) * 16 + gg];
        q += g_gnpart[((b << 6) + tile) * 16 + 8 + gg];
    }
    const float inv_n = 1.f / 147456.f;  // 9 channels * 128*128
    float m = s * inv_n;
    float v = fmaf(q, inv_n, -m * m);
    g_gnstat[t * 2]     = m;
    g_gnstat[t * 2 + 1] = rsqrtf(v + 1e-5f);
}

// ---------------- Pass B: GN-normalize weights + per-pixel local 3x3 conv --
#define SMEMB (64 * 324 * 4)

__global__ void __launch_bounds__(256, 1) passB(float* __restrict__ out)
{
    extern __shared__ float xt[];
    const int tid = threadIdx.x;
    const int b = blockIdx.z;
    const int ty0 = blockIdx.y << 4, tx0 = blockIdx.x << 4;
    const float* xvb = g_xv + (size_t)b * 64 * HW;

    for (int i = tid; i < 64 * 324; i += 256) {
        int c = i / 324; int r = i - c * 324;
        int yy = r / 18, xx = r - yy * 18;
        int gy = ty0 + yy - 1, gx = tx0 + xx - 1;
        float v = 0.f;
        if ((unsigned)gy < 128u && (unsigned)gx < 128u)
            v = __ldg(xvb + (c << 14) + (gy << 7) + gx);
        xt[i] = v;
    }
    __syncthreads();

    const int lty = tid >> 4, ltx = tid & 15;
    const int pix = ((ty0 + lty) << 7) + (tx0 + ltx);

    #pragma unroll
    for (int half = 0; half < 2; half++) {
        #pragma unroll
        for (int g4 = 0; g4 < 4; g4++) {
            const int gg = half * 4 + g4;
            float mean = g_gnstat[(b * 8 + gg) * 2];
            float rstd = g_gnstat[(b * 8 + gg) * 2 + 1];
            float wn[9];
            #pragma unroll
            for (int t = 0; t < 9; t++) {
                int o2 = half * 36 + g4 * 9 + t;
                float raw = g_wraw[((b * 72 + o2) << 14) + pix];
                wn[t] = fmaf((raw - mean) * rstd, c_gnw[o2], c_gnb[o2]);
            }
            for (int cc = 0; cc < 8; cc++) {
                int c = half * 32 + g4 * 8 + cc;
                const float* pc = xt + c * 324 + lty * 18 + ltx;
                float a = 0.f;
                #pragma unroll
                for (int dy = 0; dy < 3; dy++)
                    #pragma unroll
                    for (int dx = 0; dx < 3; dx++)
                        a = fmaf(pc[dy * 18 + dx], wn[dy * 3 + dx], a);
                out[((b << 6) + c) * HW + pix] = a;
            }
        }
    }
}

// ---------------- channel sums (for attention) ------------------------------
__global__ void chanSumK(const float* __restrict__ out)
{
    int plane = blockIdx.x;            // b*64 + c
    const float4* p = (const float4*)(out + (size_t)plane * HW);
    int tid = threadIdx.x;
    float s = 0.f;
    for (int i = tid; i < HW / 4; i += 256) {
        float4 v = p[i];
        s += v.x + v.y + v.z + v.w;
    }
    #pragma unroll
    for (int off = 16; off; off >>= 1) s += __shfl_xor_sync(0xffffffffu, s, off);
    __shared__ float sw[8];
    if ((tid & 31) == 0) sw[tid >> 5] = s;
    __syncthreads();
    if (tid == 0) {
        float t = 0.f;
        #pragma unroll
        for (int w = 0; w < 8; w++) t += sw[w];
        g_chansum[plane] = t;
    }
}

// ---------------- channel attention MLP -------------------------------------
__global__ void attnK()
{
    int b = blockIdx.x;
    int c = threadIdx.x;               // 64 threads
    __shared__ float m[64], t4[4];
    m[c] = g_chansum[(b << 6) + c] * (1.f / 16384.f);
    __syncthreads();
    if (c < 4) {
        float a = 0.f;
        for (int i = 0; i < 64; i++) a = fmaf(m[i], c_wdu1[c * 64 + i], a);
        t4[c] = fmaxf(a, 0.f);
    }
    __syncthreads();
    float a = 0.f;
    #pragma unroll
    for (int j = 0; j < 4; j++) a = fmaf(t4[j], c_wdu2[c * 4 + j], a);
    g_yscale[(b << 6) + c] = 1.f / (1.f + expf(-a));
}

// ---------------- final scale ------------------------------------------------
__global__ void scaleK(float* __restrict__ out)
{
    int i = blockIdx.x * blockDim.x + threadIdx.x;   // float4 index
    float4* p = (float4*)out;
    float s = g_yscale[i >> 12];                     // 4096 float4 per plane
    float4 v = p[i];
    v.x *= s; v.y *= s; v.z *= s; v.w *= s;
    p[i] = v;
}

// ---------------- launcher ----------------------------------------------------
extern "C" void kernel_launch(void* const* d_in, const int* in_sizes, int n_in,
                              void* d_out, int out_size)
{
    const float* x    = (const float*)d_in[0];
    const float* wkey = (const float*)d_in[1];
    const float* we1  = (const float*)d_in[2];
    const float* we2  = (const float*)d_in[3];
    const float* be2  = (const float*)d_in[4];
    const float* gnw  = (const float*)d_in[5];
    const float* gnb  = (const float*)d_in[6];
    const float* wc1  = (const float*)d_in[7];
    const float* wdu1 = (const float*)d_in[8];
    const float* wdu2 = (const float*)d_in[9];
    float* out = (float*)d_out;

    cudaMemcpyToSymbolAsync(c_gnw,  gnw,  72 * 4,  0, cudaMemcpyDeviceToDevice, 0);
    cudaMemcpyToSymbolAsync(c_gnb,  gnb,  72 * 4,  0, cudaMemcpyDeviceToDevice, 0);
    cudaMemcpyToSymbolAsync(c_wdu1, wdu1, 256 * 4, 0, cudaMemcpyDeviceToDevice, 0);
    cudaMemcpyToSymbolAsync(c_wdu2, wdu2, 256 * 4, 0, cudaMemcpyDeviceToDevice, 0);

    cudaFuncSetAttribute(passA, cudaFuncAttributeMaxDynamicSharedMemorySize, SMEMA);
    cudaFuncSetAttribute(passB, cudaFuncAttributeMaxDynamicSharedMemorySize, SMEMB);

    dim3 grid(8, 8, 8);
    passA<<<grid, 256, SMEMA>>>(x, wkey, we1, we2, be2, wc1);
    statsK<<<1, 64>>>();
    passB<<<grid, 256, SMEMB>>>(out);
    chanSumK<<<512, 256>>>(out);
    attnK<<<8, 64>>>();
    scaleK<<<8192, 256>>>(out);
}

// round 2
// speedup vs baseline: 1.1934x; 1.1934x over previous
#include <cuda_runtime.h>

#define HW 16384
#define TILE_W 32
#define TILE_H 16
#define XSTR 35            // padded row stride (odd vs 32 banks)
#define CSTR 630           // 18 * 35
#define XT_SZ 40320        // 64 * 630

// ---------------- scratch ----------------------------------------------------
__device__ float g_wraw[8 * 72 * HW];
__device__ float g_xv[8 * 64 * HW];
__device__ float g_gnpart[256 * 16];
__device__ float g_gnstat[64 * 2];
__device__ float g_chanpart[256 * 64];
__device__ float g_yscale[512];

__constant__ float c_gnw[72], c_gnb[72], c_wdu1[256], c_wdu2[256];

// ---------------- passA smem layout (float offsets) -------------------------
#define WK  0              // 6144: padded [ (oc*8+ci)*12 + t ]
#define WE1 6144           // 2048: transposed [ ((h*32+m)*16+o)*2 + s ]
#define WE2 8192           // 1152
#define BE2 9344           // 72
#define WC1 9416           // 2048
#define XTA 11472
#define SMEMA ((XTA + XT_SZ) * 4)

__global__ void __launch_bounds__(256, 1) passA(
    const float* __restrict__ x, const float* __restrict__ wkey,
    const float* __restrict__ we1, const float* __restrict__ we2,
    const float* __restrict__ be2, const float* __restrict__ wc1)
{
    extern __shared__ float sm[];
    const int tid = threadIdx.x;

    // key conv weights, padded rows of 12 for LDS.128
    for (int i = tid; i < 4608; i += 256) {
        int oc = i / 72, r = i - oc * 72, ci = r / 9, t = r - ci * 9;
        sm[WK + (oc * 8 + ci) * 12 + t] = wkey[i];
    }
    // e1 weights transposed: per (half,m) the 16 (w_x,w_k) pairs
    for (int i = tid; i < 2048; i += 256) {
        int h = i >> 10, rem = i & 1023, o = rem >> 6, ic = rem & 63;
        sm[WE1 + (((h * 32 + (ic >> 1)) * 16 + o) << 1) + (ic & 1)] = we1[i];
    }
    for (int i = tid; i < 1152; i += 256) sm[WE2 + i] = we2[i];
    if (tid < 72) sm[BE2 + tid] = be2[tid];
    for (int i = tid; i < 2048; i += 256) sm[WC1 + i] = wc1[i];

    const int b = blockIdx.z;
    const int ty0 = blockIdx.y * TILE_H, tx0 = blockIdx.x * TILE_W;
    const float* xb = x + (size_t)b * 64 * HW;
    float* xt = sm + XTA;

    // x tile with halo: [64][18][35(padded)]
    for (int i = tid; i < XT_SZ; i += 256) {
        int c = i / CSTR, r = i - c * CSTR, yy = r / XSTR, xx = r - yy * XSTR;
        int gy = ty0 + yy - 1, gx = tx0 + xx - 1;
        float v = 0.f;
        if ((unsigned)gy < 128u && (unsigned)gx < 128u)
            v = __ldg(xb + (c << 14) + (gy << 7) + gx);
        xt[i] = v;
    }
    __syncthreads();

    const int lty = tid >> 4, lx0 = (tid & 15) << 1;
    const int pix = ((ty0 + lty) << 7) + tx0 + lx0;

    float lsum[8], lsq[8];

    #pragma unroll
    for (int half = 0; half < 2; half++) {
        float acc[32];
        #pragma unroll
        for (int o = 0; o < 32; o++) acc[o] = 0.f;

        #pragma unroll 1
        for (int g4 = 0; g4 < 4; g4++) {
            const int g = half * 4 + g4;
            float kk[16];
            #pragma unroll
            for (int i = 0; i < 16; i++) kk[i] = 0.f;

            // grouped 3x3 key conv, 2 pixels per thread, 16 indep chains
            #pragma unroll 1
            for (int ci = 0; ci < 8; ci++) {
                const float* pb = xt + (g * 8 + ci) * CSTR + lty * XSTR + lx0;
                float pr[12];
                #pragma unroll
                for (int dy = 0; dy < 3; dy++)
                    #pragma unroll
                    for (int dx = 0; dx < 4; dx++)
                        pr[dy * 4 + dx] = pb[dy * XSTR + dx];
                const float* wb = sm + WK + (g * 64 + ci) * 12;
                #pragma unroll
                for (int oc = 0; oc < 8; oc++) {
                    const float4* w4 = (const float4*)(wb + oc * 96);
                    float4 wa = w4[0], wc = w4[1];
                    float w8 = wb[oc * 96 + 8];
                    float wv[9] = {wa.x, wa.y, wa.z, wa.w, wc.x, wc.y, wc.z, wc.w, w8};
                    #pragma unroll
                    for (int t = 0; t < 9; t++) {
                        int pi = (t / 3) * 4 + (t % 3);
                        kk[oc * 2]     = fmaf(pr[pi],     wv[t], kk[oc * 2]);
                        kk[oc * 2 + 1] = fmaf(pr[pi + 1], wv[t], kk[oc * 2 + 1]);
                    }
                }
            }
            // e1: interleaved (x, relu(k)) contributions
            #pragma unroll 1
            for (int ci = 0; ci < 8; ci++) {
                const float* ctr = xt + (g * 8 + ci) * CSTR + (lty + 1) * XSTR + lx0 + 1;
                float xc0 = ctr[0], xc1 = ctr[1];
                float kv0 = fmaxf(kk[ci * 2], 0.f), kv1 = fmaxf(kk[ci * 2 + 1], 0.f);
                const float2* w1 = (const float2*)(sm + WE1 +
                                    ((half * 32 + g4 * 8 + ci) << 5));
                #pragma unroll
                for (int o = 0; o < 16; o++) {
                    float2 w = w1[o];
                    acc[o * 2]     = fmaf(xc0, w.x, fmaf(kv0, w.y, acc[o * 2]));
                    acc[o * 2 + 1] = fmaf(xc1, w.x, fmaf(kv1, w.y, acc[o * 2 + 1]));
                }
            }
        }
        #pragma unroll
        for (int o = 0; o < 32; o++) acc[o] = fmaxf(acc[o], 0.f);

        // e2 + GN partial sums + wraw store (float2)
        #pragma unroll
        for (int g4 = 0; g4 < 4; g4++) {
            const int gg = half * 4 + g4;
            float s = 0.f, q = 0.f;
            #pragma unroll
            for (int j = 0; j < 9; j++) {
                const int o2 = gg * 9 + j;
                const float4* w2 = (const float4*)(sm + WE2 + o2 * 16);
                float a0 = sm[BE2 + o2], a1 = a0;
                #pragma unroll
                for (int qq = 0; qq < 4; qq++) {
                    float4 w = w2[qq];
                    a0 = fmaf(acc[(qq * 4 + 0) * 2], w.x, a0);
                    a0 = fmaf(acc[(qq * 4 + 1) * 2], w.y, a0);
                    a0 = fmaf(acc[(qq * 4 + 2) * 2], w.z, a0);
                    a0 = fmaf(acc[(qq * 4 + 3) * 2], w.w, a0);
                    a1 = fmaf(acc[(qq * 4 + 0) * 2 + 1], w.x, a1);
                    a1 = fmaf(acc[(qq * 4 + 1) * 2 + 1], w.y, a1);
                    a1 = fmaf(acc[(qq * 4 + 2) * 2 + 1], w.z, a1);
                    a1 = fmaf(acc[(qq * 4 + 3) * 2 + 1], w.w, a1);
                }
                *(float2*)(g_wraw + (((size_t)b * 72 + o2) << 14) + pix) =
                    make_float2(a0, a1);
                s += a0 + a1;
                q = fmaf(a0, a0, q); q = fmaf(a1, a1, q);
            }
            lsum[gg] = s; lsq[gg] = q;
        }
    }

    // xv = grouped conv1x1(x), float2 stores
    #pragma unroll
    for (int grp = 0; grp < 2; grp++) {
        float xin[64];
        #pragma unroll
        for (int ic = 0; ic < 32; ic++) {
            const float* ctr = xt + (grp * 32 + ic) * CSTR + (lty + 1) * XSTR + lx0 + 1;
            xin[ic * 2] = ctr[0]; xin[ic * 2 + 1] = ctr[1];
        }
        #pragma unroll 1
        for (int ocb = 0; ocb < 4; ocb++) {
            float a8[16];
            #pragma unroll
            for (int i = 0; i < 16; i++) a8[i] = 0.f;
            #pragma unroll
            for (int oc8 = 0; oc8 < 8; oc8++) {
                const float4* w = (const float4*)(sm + WC1 + (grp * 32 + ocb * 8 + oc8) * 32);
                #pragma unroll
                for (int qq = 0; qq < 8; qq++) {
                    float4 wv = w[qq];
                    a8[oc8 * 2]     = fmaf(xin[(qq * 4 + 0) * 2], wv.x, a8[oc8 * 2]);
                    a8[oc8 * 2]     = fmaf(xin[(qq * 4 + 1) * 2], wv.y, a8[oc8 * 2]);
                    a8[oc8 * 2]     = fmaf(xin[(qq * 4 + 2) * 2], wv.z, a8[oc8 * 2]);
                    a8[oc8 * 2]     = fmaf(xin[(qq * 4 + 3) * 2], wv.w, a8[oc8 * 2]);
                    a8[oc8 * 2 + 1] = fmaf(xin[(qq * 4 + 0) * 2 + 1], wv.x, a8[oc8 * 2 + 1]);
                    a8[oc8 * 2 + 1] = fmaf(xin[(qq * 4 + 1) * 2 + 1], wv.y, a8[oc8 * 2 + 1]);
                    a8[oc8 * 2 + 1] = fmaf(xin[(qq * 4 + 2) * 2 + 1], wv.z, a8[oc8 * 2 + 1]);
                    a8[oc8 * 2 + 1] = fmaf(xin[(qq * 4 + 3) * 2 + 1], wv.w, a8[oc8 * 2 + 1]);
                }
            }
            #pragma unroll
            for (int oc8 = 0; oc8 < 8; oc8++)
                *(float2*)(g_xv + (((size_t)b * 64 + grp * 32 + ocb * 8 + oc8) << 14) + pix) =
                    make_float2(a8[oc8 * 2], a8[oc8 * 2 + 1]);
        }
    }

    // GN partial reduce (deterministic)
    __syncthreads();
    #pragma unroll
    for (int off = 16; off; off >>= 1)
        #pragma unroll
        for (int gg = 0; gg < 8; gg++) {
            lsum[gg] += __shfl_xor_sync(0xffffffffu, lsum[gg], off);
            lsq[gg]  += __shfl_xor_sync(0xffffffffu, lsq[gg],  off);
        }
    const int wid = tid >> 5, lane = tid & 31;
    if (lane == 0) {
        #pragma unroll
        for (int gg = 0; gg < 8; gg++) {
            sm[wid * 16 + gg] = lsum[gg];
            sm[wid * 16 + 8 + gg] = lsq[gg];
        }
    }
    __syncthreads();
    if (tid < 16) {
        float s = 0.f;
        #pragma unroll
        for (int w = 0; w < 8; w++) s += sm[w * 16 + tid];
        g_gnpart[(b * 32 + blockIdx.y * 4 + blockIdx.x) * 16 + tid] = s;
    }
}

// ---------------- GN stats ----------------------------------------------------
__global__ void statsK()
{
    int t = threadIdx.x;
    if (t >= 64) return;
    int b = t >> 3, gg = t & 7;
    float s = 0.f, q = 0.f;
    for (int tile = 0; tile < 32; tile++) {
        s += g_gnpart[(b * 32 + tile) * 16 + gg];
        q += g_gnpart[(b * 32 + tile) * 16 + 8 + gg];
    }
    const float inv_n = 1.f / 147456.f;
    float m = s * inv_n;
    float v = fmaf(q, inv_n, -m * m);
    g_gnstat[t * 2] = m;
    g_gnstat[t * 2 + 1] = rsqrtf(v + 1e-5f);
}

// ---------------- passB: normalize weights + local 3x3 conv + chan partials ---
#define SCOFF 16
#define XTB 528
#define SMEMB ((XTB + XT_SZ) * 4)

__global__ void __launch_bounds__(256, 1) passB(float* __restrict__ out)
{
    extern __shared__ float sm[];
    const int tid = threadIdx.x, b = blockIdx.z;
    const int ty0 = blockIdx.y * TILE_H, tx0 = blockIdx.x * TILE_W;

    if (tid < 16) sm[tid] = g_gnstat[b * 16 + tid];
    for (int i = tid; i < 512; i += 256) sm[SCOFF + i] = 0.f;

    float* xt = sm + XTB;
    const float* xvb = g_xv + (size_t)b * 64 * HW;
    for (int i = tid; i < XT_SZ; i += 256) {
        int c = i / CSTR, r = i - c * CSTR, yy = r / XSTR, xx = r - yy * XSTR;
        int gy = ty0 + yy - 1, gx = tx0 + xx - 1;
        float v = 0.f;
        if ((unsigned)gy < 128u && (unsigned)gx < 128u)
            v = __ldg(xvb + (c << 14) + (gy << 7) + gx);
        xt[i] = v;
    }
    __syncthreads();

    const int lty = tid >> 4, lx0 = (tid & 15) << 1;
    const int pix = ((ty0 + lty) << 7) + tx0 + lx0;
    const int wid = tid >> 5;

    #pragma unroll
    for (int gg = 0; gg < 8; gg++) {
        float mean = sm[gg * 2], rstd = sm[gg * 2 + 1];
        float wn0[9], wn1[9];
        #pragma unroll
        for (int t = 0; t < 9; t++) {
            int o2 = gg * 9 + t;
            float2 raw = *(const float2*)(g_wraw + (((size_t)b * 72 + o2) << 14) + pix);
            wn0[t] = fmaf((raw.x - mean) * rstd, c_gnw[o2], c_gnb[o2]);
            wn1[t] = fmaf((raw.y - mean) * rstd, c_gnw[o2], c_gnb[o2]);
        }
        #pragma unroll 1
        for (int cc = 0; cc < 8; cc++) {
            int c = (gg >> 2) * 32 + (gg & 3) * 8 + cc;
            const float* pb = xt + c * CSTR + lty * XSTR + lx0;
            float a0 = 0.f, a1 = 0.f;
            #pragma unroll
            for (int dy = 0; dy < 3; dy++)
                #pragma unroll
                for (int dx = 0; dx < 3; dx++) {
                    float v0 = pb[dy * XSTR + dx];
                    float v1 = pb[dy * XSTR + dx + 1];
                    a0 = fmaf(v0, wn0[dy * 3 + dx], a0);
                    a1 = fmaf(v1, wn1[dy * 3 + dx], a1);
                }
            *(float2*)(out + (((size_t)b * 64 + c) << 14) + pix) = make_float2(a0, a1);
            float s = a0 + a1;
            #pragma unroll
            for (int off = 16; off; off >>= 1)
                s += __shfl_xor_sync(0xffffffffu, s, off);
            if ((tid & 31) == 0) sm[SCOFF + wid * 64 + c] += s;
        }
    }
    __syncthreads();
    if (tid < 64) {
        float s = 0.f;
        #pragma unroll
        for (int w = 0; w < 8; w++) s += sm[SCOFF + w * 64 + tid];
        g_chanpart[(b * 32 + blockIdx.y * 4 + blockIdx.x) * 64 + tid] = s;
    }
}

// ---------------- attention (tile-sum + MLP) -----------------------------------
__global__ void attnK()
{
    int b = blockIdx.x, c = threadIdx.x;
    __shared__ float m[64], t4[4];
    float s = 0.f;
    for (int t = 0; t < 32; t++) s += g_chanpart[(b * 32 + t) * 64 + c];
    m[c] = s * (1.f / 16384.f);
    __syncthreads();
    if (c < 4) {
        float a = 0.f;
        for (int i = 0; i < 64; i++) a = fmaf(m[i], c_wdu1[c * 64 + i], a);
        t4[c] = fmaxf(a, 0.f);
    }
    __syncthreads();
    float a = 0.f;
    #pragma unroll
    for (int j = 0; j < 4; j++) a = fmaf(t4[j], c_wdu2[c * 4 + j], a);
    g_yscale[b * 64 + c] = 1.f / (1.f + expf(-a));
}

// ---------------- final scale ---------------------------------------------------
__global__ void scaleK(float* __restrict__ out)
{
    int i = blockIdx.x * blockDim.x + threadIdx.x;
    float4* p = (float4*)out;
    float s = g_yscale[i >> 12];
    float4 v = p[i];
    v.x *= s; v.y *= s; v.z *= s; v.w *= s;
    p[i] = v;
}

// ---------------- launcher -------------------------------------------------------
extern "C" void kernel_launch(void* const* d_in, const int* in_sizes, int n_in,
                              void* d_out, int out_size)
{
    const float* x    = (const float*)d_in[0];
    const float* wkey = (const float*)d_in[1];
    const float* we1  = (const float*)d_in[2];
    const float* we2  = (const float*)d_in[3];
    const float* be2  = (const float*)d_in[4];
    const float* gnw  = (const float*)d_in[5];
    const float* gnb  = (const float*)d_in[6];
    const float* wc1  = (const float*)d_in[7];
    const float* wdu1 = (const float*)d_in[8];
    const float* wdu2 = (const float*)d_in[9];
    float* out = (float*)d_out;

    cudaMemcpyToSymbolAsync(c_gnw,  gnw,  72 * 4,  0, cudaMemcpyDeviceToDevice, 0);
    cudaMemcpyToSymbolAsync(c_gnb,  gnb,  72 * 4,  0, cudaMemcpyDeviceToDevice, 0);
    cudaMemcpyToSymbolAsync(c_wdu1, wdu1, 256 * 4, 0, cudaMemcpyDeviceToDevice, 0);
    cudaMemcpyToSymbolAsync(c_wdu2, wdu2, 256 * 4, 0, cudaMemcpyDeviceToDevice, 0);

    cudaFuncSetAttribute(passA, cudaFuncAttributeMaxDynamicSharedMemorySize, SMEMA);
    cudaFuncSetAttribute(passB, cudaFuncAttributeMaxDynamicSharedMemorySize, SMEMB);

    dim3 grid(4, 8, 8);
    passA<<<grid, 256, SMEMA>>>(x, wkey, we1, we2, be2, wc1);
    statsK<<<1, 64>>>();
    passB<<<grid, 256, SMEMB>>>(out);
    attnK<<<8, 64>>>();
    scaleK<<<8192, 256>>>(out);
}

// round 3
// speedup vs baseline: 1.6283x; 1.3644x over previous
#include <cuda_runtime.h>

#define HW 16384
#define TILE_W 32
#define TILE_H 16
#define XSTR 35            // padded row stride
#define CSTR 630           // 18 * 35
#define XT_SZ_H 20160      // 32 channels * 630

// ---------------- scratch ----------------------------------------------------
__device__ float g_wraw[8 * 72 * HW];
__device__ float g_xv[8 * 64 * HW];
__device__ float g_gnpart[256 * 16];
__device__ float g_gnstat[64 * 2];
__device__ float g_chanpart[256 * 64];
__device__ float g_yscale[512];

__constant__ float c_gnw[72], c_gnb[72], c_wdu1[256], c_wdu2[256];

// ---------------- passA smem layout (float offsets), per half ----------------
#define WK  0              // 3072: [(oc_l*8+ci)*12 + t], oc_l in [0,32)
#define WE1 3072           // 1024: [(m*16+o)*2 + s], m in [0,32)
#define WE2 4096           // 576
#define BE2 4672           // 36 (pad 40)
#define WC1 4712           // 1024
#define XTA 5736
#define SMEMA ((XTA + XT_SZ_H) * 4)

__global__ void __launch_bounds__(256, 2) passA(
    const float* __restrict__ x, const float* __restrict__ wkey,
    const float* __restrict__ we1, const float* __restrict__ we2,
    const float* __restrict__ be2, const float* __restrict__ wc1)
{
    extern __shared__ float sm[];
    const int tid = threadIdx.x;
    const int b = blockIdx.z >> 1, half = blockIdx.z & 1;

    // half of key conv weights, padded rows of 12
    for (int i = tid; i < 2304; i += 256) {
        int oc = i / 72, r = i - oc * 72, ci = r / 9, t = r - ci * 9;
        sm[WK + (oc * 8 + ci) * 12 + t] = wkey[(half * 32 + oc) * 72 + r];
    }
    // half of e1 weights, transposed to [m][o][2]
    for (int i = tid; i < 1024; i += 256) {
        int o = i >> 6, ic = i & 63;
        sm[WE1 + (((ic >> 1) * 16 + o) << 1) + (ic & 1)] = we1[half * 1024 + i];
    }
    for (int i = tid; i < 576; i += 256) sm[WE2 + i] = we2[half * 576 + i];
    if (tid < 36) sm[BE2 + tid] = be2[half * 36 + tid];
    for (int i = tid; i < 1024; i += 256) sm[WC1 + i] = wc1[half * 1024 + i];

    const int ty0 = blockIdx.y * TILE_H, tx0 = blockIdx.x * TILE_W;
    const float* xb = x + (size_t)b * 64 * HW + ((size_t)half << 19); // half*32*HW
    float* xt = sm + XTA;

    // 32-channel x tile with halo: [32][18][35]
    for (int i = tid; i < XT_SZ_H; i += 256) {
        int c = i / CSTR, r = i - c * CSTR, yy = r / XSTR, xx = r - yy * XSTR;
        int gy = ty0 + yy - 1, gx = tx0 + xx - 1;
        float v = 0.f;
        if ((unsigned)gy < 128u && (unsigned)gx < 128u)
            v = __ldg(xb + (c << 14) + (gy << 7) + gx);
        xt[i] = v;
    }
    __syncthreads();

    const int lty = tid >> 4, lx0 = (tid & 15) << 1;
    const int pix = ((ty0 + lty) << 7) + tx0 + lx0;

    float acc[32];
    #pragma unroll
    for (int o = 0; o < 32; o++) acc[o] = 0.f;

    #pragma unroll 1
    for (int g4 = 0; g4 < 4; g4++) {
        float kk[16];
        #pragma unroll
        for (int i = 0; i < 16; i++) kk[i] = 0.f;

        // grouped 3x3 key conv, 2 px per thread, 16 indep chains
        #pragma unroll 1
        for (int ci = 0; ci < 8; ci++) {
            const float* pb = xt + (g4 * 8 + ci) * CSTR + lty * XSTR + lx0;
            float pr[12];
            #pragma unroll
            for (int dy = 0; dy < 3; dy++)
                #pragma unroll
                for (int dx = 0; dx < 4; dx++)
                    pr[dy * 4 + dx] = pb[dy * XSTR + dx];
            const float* wb = sm + WK + (g4 * 64 + ci) * 12;
            #pragma unroll
            for (int oc = 0; oc < 8; oc++) {
                const float4* w4 = (const float4*)(wb + oc * 96);
                float4 wa = w4[0], wc = w4[1];
                float w8 = wb[oc * 96 + 8];
                float wv[9] = {wa.x, wa.y, wa.z, wa.w, wc.x, wc.y, wc.z, wc.w, w8};
                #pragma unroll
                for (int t = 0; t < 9; t++) {
                    int pi = (t / 3) * 4 + (t % 3);
                    kk[oc * 2]     = fmaf(pr[pi],     wv[t], kk[oc * 2]);
                    kk[oc * 2 + 1] = fmaf(pr[pi + 1], wv[t], kk[oc * 2 + 1]);
                }
            }
        }
        // e1 contributions (x, relu(k))
        #pragma unroll 1
        for (int ci = 0; ci < 8; ci++) {
            const float* ctr = xt + (g4 * 8 + ci) * CSTR + (lty + 1) * XSTR + lx0 + 1;
            float xc0 = ctr[0], xc1 = ctr[1];
            float kv0 = fmaxf(kk[ci * 2], 0.f), kv1 = fmaxf(kk[ci * 2 + 1], 0.f);
            const float2* w1 = (const float2*)(sm + WE1 + ((g4 * 8 + ci) << 5));
            #pragma unroll
            for (int o = 0; o < 16; o++) {
                float2 w = w1[o];
                acc[o * 2]     = fmaf(xc0, w.x, fmaf(kv0, w.y, acc[o * 2]));
                acc[o * 2 + 1] = fmaf(xc1, w.x, fmaf(kv1, w.y, acc[o * 2 + 1]));
            }
        }
    }
    #pragma unroll
    for (int o = 0; o < 32; o++) acc[o] = fmaxf(acc[o], 0.f);

    // e2 + GN partials + wraw store
    float lsum[4], lsq[4];
    #pragma unroll
    for (int g4 = 0; g4 < 4; g4++) {
        float s = 0.f, q = 0.f;
        #pragma unroll
        for (int j = 0; j < 9; j++) {
            const int o2l = g4 * 9 + j;
            const float4* w2 = (const float4*)(sm + WE2 + o2l * 16);
            float a0 = sm[BE2 + o2l], a1 = a0;
            #pragma unroll
            for (int qq = 0; qq < 4; qq++) {
                float4 w = w2[qq];
                a0 = fmaf(acc[(qq * 4 + 0) * 2], w.x, a0);
                a0 = fmaf(acc[(qq * 4 + 1) * 2], w.y, a0);
                a0 = fmaf(acc[(qq * 4 + 2) * 2], w.z, a0);
                a0 = fmaf(acc[(qq * 4 + 3) * 2], w.w, a0);
                a1 = fmaf(acc[(qq * 4 + 0) * 2 + 1], w.x, a1);
                a1 = fmaf(acc[(qq * 4 + 1) * 2 + 1], w.y, a1);
                a1 = fmaf(acc[(qq * 4 + 2) * 2 + 1], w.z, a1);
                a1 = fmaf(acc[(qq * 4 + 3) * 2 + 1], w.w, a1);
            }
            *(float2*)(g_wraw + (((size_t)b * 72 + half * 36 + o2l) << 14) + pix) =
                make_float2(a0, a1);
            s += a0 + a1;
            q = fmaf(a0, a0, q); q = fmaf(a1, a1, q);
        }
        lsum[g4] = s; lsq[g4] = q;
    }

    // xv = grouped conv1x1 (this half's group)
    {
        float xin[64];
        #pragma unroll
        for (int ic = 0; ic < 32; ic++) {
            const float* ctr = xt + ic * CSTR + (lty + 1) * XSTR + lx0 + 1;
            xin[ic * 2] = ctr[0]; xin[ic * 2 + 1] = ctr[1];
        }
        #pragma unroll 1
        for (int ocb = 0; ocb < 4; ocb++) {
            float a8[16];
            #pragma unroll
            for (int i = 0; i < 16; i++) a8[i] = 0.f;
            #pragma unroll
            for (int oc8 = 0; oc8 < 8; oc8++) {
                const float4* w = (const float4*)(sm + WC1 + (ocb * 8 + oc8) * 32);
                #pragma unroll
                for (int qq = 0; qq < 8; qq++) {
                    float4 wv = w[qq];
                    a8[oc8 * 2]     = fmaf(xin[(qq * 4 + 0) * 2], wv.x, a8[oc8 * 2]);
                    a8[oc8 * 2]     = fmaf(xin[(qq * 4 + 1) * 2], wv.y, a8[oc8 * 2]);
                    a8[oc8 * 2]     = fmaf(xin[(qq * 4 + 2) * 2], wv.z, a8[oc8 * 2]);
                    a8[oc8 * 2]     = fmaf(xin[(qq * 4 + 3) * 2], wv.w, a8[oc8 * 2]);
                    a8[oc8 * 2 + 1] = fmaf(xin[(qq * 4 + 0) * 2 + 1], wv.x, a8[oc8 * 2 + 1]);
                    a8[oc8 * 2 + 1] = fmaf(xin[(qq * 4 + 1) * 2 + 1], wv.y, a8[oc8 * 2 + 1]);
                    a8[oc8 * 2 + 1] = fmaf(xin[(qq * 4 + 2) * 2 + 1], wv.z, a8[oc8 * 2 + 1]);
                    a8[oc8 * 2 + 1] = fmaf(xin[(qq * 4 + 3) * 2 + 1], wv.w, a8[oc8 * 2 + 1]);
                }
            }
            #pragma unroll
            for (int oc8 = 0; oc8 < 8; oc8++)
                *(float2*)(g_xv + (((size_t)b * 64 + half * 32 + ocb * 8 + oc8) << 14) + pix) =
                    make_float2(a8[oc8 * 2], a8[oc8 * 2 + 1]);
        }
    }

    // GN partial reduce
    __syncthreads();
    #pragma unroll
    for (int off = 16; off; off >>= 1)
        #pragma unroll
        for (int g4 = 0; g4 < 4; g4++) {
            lsum[g4] += __shfl_xor_sync(0xffffffffu, lsum[g4], off);
            lsq[g4]  += __shfl_xor_sync(0xffffffffu, lsq[g4],  off);
        }
    const int wid = tid >> 5, lane = tid & 31;
    if (lane == 0) {
        #pragma unroll
        for (int g4 = 0; g4 < 4; g4++) {
            sm[wid * 8 + g4] = lsum[g4];
            sm[wid * 8 + 4 + g4] = lsq[g4];
        }
    }
    __syncthreads();
    if (tid < 8) {
        float s = 0.f;
        #pragma unroll
        for (int w = 0; w < 8; w++) s += sm[w * 8 + tid];
        int slot = (b * 32 + blockIdx.y * 4 + blockIdx.x) * 16;
        int e = (tid < 4) ? (half * 4 + tid) : (8 + half * 4 + tid - 4);
        g_gnpart[slot + e] = s;
    }
}

// ---------------- GN stats (parallel) ----------------------------------------
__global__ void statsK()
{
    int tid = threadIdx.x;             // 512 threads
    int idx = tid >> 3, k = tid & 7;   // idx=(b,gg), k=tile chunk
    int b = idx >> 3, gg = idx & 7;
    float s = 0.f, q = 0.f;
    #pragma unroll
    for (int t = 0; t < 4; t++) {
        int tile = k * 4 + t;
        s += g_gnpart[(b * 32 + tile) * 16 + gg];
        q += g_gnpart[(b * 32 + tile) * 16 + 8 + gg];
    }
    #pragma unroll
    for (int off = 4; off; off >>= 1) {
        s += __shfl_xor_sync(0xffffffffu, s, off);
        q += __shfl_xor_sync(0xffffffffu, q, off);
    }
    if (k == 0) {
        const float inv_n = 1.f / 147456.f;
        float m = s * inv_n;
        float v = fmaf(q, inv_n, -m * m);
        g_gnstat[idx * 2] = m;
        g_gnstat[idx * 2 + 1] = rsqrtf(v + 1e-5f);
    }
}

// ---------------- passB (half-split) ------------------------------------------
#define ST  0              // 8 stats
#define SC  8              // 8 warps * 32 channel partials
#define XTB 264
#define SMEMB ((XTB + XT_SZ_H) * 4)

__global__ void __launch_bounds__(256, 2) passB(float* __restrict__ out)
{
    extern __shared__ float sm[];
    const int tid = threadIdx.x;
    const int b = blockIdx.z >> 1, half = blockIdx.z & 1;
    const int ty0 = blockIdx.y * TILE_H, tx0 = blockIdx.x * TILE_W;

    if (tid < 8) sm[ST + tid] = g_gnstat[b * 16 + half * 8 + tid];
    if (tid < 256) sm[SC + tid] = 0.f;

    float* xt = sm + XTB;
    const float* xvb = g_xv + (size_t)b * 64 * HW + ((size_t)half << 19);
    for (int i = tid; i < XT_SZ_H; i += 256) {
        int c = i / CSTR, r = i - c * CSTR, yy = r / XSTR, xx = r - yy * XSTR;
        int gy = ty0 + yy - 1, gx = tx0 + xx - 1;
        float v = 0.f;
        if ((unsigned)gy < 128u && (unsigned)gx < 128u)
            v = __ldg(xvb + (c << 14) + (gy << 7) + gx);
        xt[i] = v;
    }
    __syncthreads();

    const int lty = tid >> 4, lx0 = (tid & 15) << 1;
    const int pix = ((ty0 + lty) << 7) + tx0 + lx0;
    const int wid = tid >> 5;

    #pragma unroll
    for (int g4 = 0; g4 < 4; g4++) {
        float mean = sm[ST + g4 * 2], rstd = sm[ST + g4 * 2 + 1];
        float wn0[9], wn1[9];
        #pragma unroll
        for (int t = 0; t < 9; t++) {
            int o2 = half * 36 + g4 * 9 + t;
            float2 raw = *(const float2*)(g_wraw + (((size_t)b * 72 + o2) << 14) + pix);
            wn0[t] = fmaf((raw.x - mean) * rstd, c_gnw[o2], c_gnb[o2]);
            wn1[t] = fmaf((raw.y - mean) * rstd, c_gnw[o2], c_gnb[o2]);
        }
        #pragma unroll 1
        for (int cc = 0; cc < 8; cc++) {
            int cl = g4 * 8 + cc;
            const float* pb = xt + cl * CSTR + lty * XSTR + lx0;
            float a0 = 0.f, a1 = 0.f;
            #pragma unroll
            for (int dy = 0; dy < 3; dy++)
                #pragma unroll
                for (int dx = 0; dx < 3; dx++) {
                    a0 = fmaf(pb[dy * XSTR + dx],     wn0[dy * 3 + dx], a0);
                    a1 = fmaf(pb[dy * XSTR + dx + 1], wn1[dy * 3 + dx], a1);
                }
            *(float2*)(out + (((size_t)b * 64 + half * 32 + cl) << 14) + pix) =
                make_float2(a0, a1);
            float s = a0 + a1;
            #pragma unroll
            for (int off = 16; off; off >>= 1)
                s += __shfl_xor_sync(0xffffffffu, s, off);
            if ((tid & 31) == 0) sm[SC + wid * 32 + cl] += s;
        }
    }
    __syncthreads();
    if (tid < 32) {
        float s = 0.f;
        #pragma unroll
        for (int w = 0; w < 8; w++) s += sm[SC + w * 32 + tid];
        g_chanpart[(b * 32 + blockIdx.y * 4 + blockIdx.x) * 64 + half * 32 + tid] = s;
    }
}

// ---------------- attention (parallel tile-sum + MLP) --------------------------
__global__ void attnK()
{
    int b = blockIdx.x, tid = threadIdx.x;     // 512 threads
    int c = tid >> 3, k = tid & 7;
    __shared__ float m[64], t4[4];
    float s = 0.f;
    #pragma unroll
    for (int t = 0; t < 4; t++)
        s += g_chanpart[(b * 32 + k * 4 + t) * 64 + c];
    #pragma unroll
    for (int off = 4; off; off >>= 1)
        s += __shfl_xor_sync(0xffffffffu, s, off);
    if (k == 0) m[c] = s * (1.f / 16384.f);
    __syncthreads();
    if (tid < 4) {
        float a = 0.f;
        for (int i = 0; i < 64; i++) a = fmaf(m[i], c_wdu1[tid * 64 + i], a);
        t4[tid] = fmaxf(a, 0.f);
    }
    __syncthreads();
    if (tid < 64) {
        float a = 0.f;
        #pragma unroll
        for (int j = 0; j < 4; j++) a = fmaf(t4[j], c_wdu2[tid * 4 + j], a);
        g_yscale[b * 64 + tid] = 1.f / (1.f + expf(-a));
    }
}

// ---------------- final scale ---------------------------------------------------
__global__ void scaleK(float* __restrict__ out)
{
    int i = blockIdx.x * blockDim.x + threadIdx.x;
    float4* p = (float4*)out;
    float s = g_yscale[i >> 12];
    float4 v = p[i];
    v.x *= s; v.y *= s; v.z *= s; v.w *= s;
    p[i] = v;
}

// ---------------- launcher -------------------------------------------------------
extern "C" void kernel_launch(void* const* d_in, const int* in_sizes, int n_in,
                              void* d_out, int out_size)
{
    const float* x    = (const float*)d_in[0];
    const float* wkey = (const float*)d_in[1];
    const float* we1  = (const float*)d_in[2];
    const float* we2  = (const float*)d_in[3];
    const float* be2  = (const float*)d_in[4];
    const float* gnw  = (const float*)d_in[5];
    const float* gnb  = (const float*)d_in[6];
    const float* wc1  = (const float*)d_in[7];
    const float* wdu1 = (const float*)d_in[8];
    const float* wdu2 = (const float*)d_in[9];
    float* out = (float*)d_out;

    cudaMemcpyToSymbolAsync(c_gnw,  gnw,  72 * 4,  0, cudaMemcpyDeviceToDevice, 0);
    cudaMemcpyToSymbolAsync(c_gnb,  gnb,  72 * 4,  0, cudaMemcpyDeviceToDevice, 0);
    cudaMemcpyToSymbolAsync(c_wdu1, wdu1, 256 * 4, 0, cudaMemcpyDeviceToDevice, 0);
    cudaMemcpyToSymbolAsync(c_wdu2, wdu2, 256 * 4, 0, cudaMemcpyDeviceToDevice, 0);

    cudaFuncSetAttribute(passA, cudaFuncAttributeMaxDynamicSharedMemorySize, SMEMA);
    cudaFuncSetAttribute(passB, cudaFuncAttributeMaxDynamicSharedMemorySize, SMEMB);

    dim3 grid(4, 8, 16);
    passA<<<grid, 256, SMEMA>>>(x, wkey, we1, we2, be2, wc1);
    statsK<<<1, 512>>>();
    passB<<<grid, 256, SMEMB>>>(out);
    attnK<<<8, 512>>>();
    scaleK<<<8192, 256>>>(out);
}

// round 4
// speedup vs baseline: 1.6869x; 1.0359x over previous
#include <cuda_runtime.h>

#define HW 16384
#define TILE_W 32
#define TILE_H 16
#define XSTR 35            // padded row stride
#define CSTR 630           // 18 * 35
#define XT_SZ_H 20160      // 32 channels * 630

typedef unsigned long long ull;

// ---------------- f32x2 helpers ------------------------------------------------
__device__ __forceinline__ ull pk2(float lo, float hi) {
    ull r; asm("mov.b64 %0,{%1,%2};" : "=l"(r) : "f"(lo), "f"(hi)); return r;
}
__device__ __forceinline__ ull dup2(float v) { return pk2(v, v); }
__device__ __forceinline__ void upk2(ull v, float& lo, float& hi) {
    asm("mov.b64 {%0,%1},%2;" : "=f"(lo), "=f"(hi) : "l"(v));
}
__device__ __forceinline__ ull f2fma(ull a, ull b, ull c) {
    ull d; asm("fma.rn.f32x2 %0,%1,%2,%3;" : "=l"(d) : "l"(a), "l"(b), "l"(c)); return d;
}
__device__ __forceinline__ ull f2add(ull a, ull b) {
    ull d; asm("add.rn.f32x2 %0,%1,%2;" : "=l"(d) : "l"(a), "l"(b)); return d;
}
__device__ __forceinline__ ull f2relu(ull v) {
    float lo, hi; upk2(v, lo, hi);
    return pk2(fmaxf(lo, 0.f), fmaxf(hi, 0.f));
}

// ---------------- scratch ----------------------------------------------------
__device__ float g_wraw[8 * 72 * HW];
__device__ float g_xv[8 * 64 * HW];
__device__ float g_gnpart[256 * 16];
__device__ float g_gnstat[64 * 2];
__device__ float g_chanpart[256 * 64];
__device__ float g_yscale[512];

__constant__ float c_gnw[72], c_gnb[72], c_wdu1[256], c_wdu2[256];

// ---------------- passA smem layout (float offsets), per half ----------------
#define WK  0              // 3072: [(oc_l*8+ci)*12 + t]
#define WE1 3072           // 1024: [(m*16+o)*2 + s]
#define WE2 4096           // 576
#define BE2 4672           // 36 (pad 40)
#define WC1 4712           // 1024
#define XTA 5736
#define SMEMA ((XTA + XT_SZ_H) * 4)

__global__ void __launch_bounds__(256, 2) passA(
    const float* __restrict__ x, const float* __restrict__ wkey,
    const float* __restrict__ we1, const float* __restrict__ we2,
    const float* __restrict__ be2, const float* __restrict__ wc1)
{
    extern __shared__ float sm[];
    const int tid = threadIdx.x;
    const int b = blockIdx.z >> 1, half = blockIdx.z & 1;

    for (int i = tid; i < 2304; i += 256) {
        int oc = i / 72, r = i - oc * 72, ci = r / 9, t = r - ci * 9;
        sm[WK + (oc * 8 + ci) * 12 + t] = wkey[(half * 32 + oc) * 72 + r];
    }
    for (int i = tid; i < 1024; i += 256) {
        int o = i >> 6, ic = i & 63;
        sm[WE1 + (((ic >> 1) * 16 + o) << 1) + (ic & 1)] = we1[half * 1024 + i];
    }
    for (int i = tid; i < 576; i += 256) sm[WE2 + i] = we2[half * 576 + i];
    if (tid < 36) sm[BE2 + tid] = be2[half * 36 + tid];
    for (int i = tid; i < 1024; i += 256) sm[WC1 + i] = wc1[half * 1024 + i];

    const int ty0 = blockIdx.y * TILE_H, tx0 = blockIdx.x * TILE_W;
    const float* xb = x + (size_t)b * 64 * HW + ((size_t)half << 19);
    float* xt = sm + XTA;

    for (int i = tid; i < XT_SZ_H; i += 256) {
        int c = i / CSTR, r = i - c * CSTR, yy = r / XSTR, xx = r - yy * XSTR;
        int gy = ty0 + yy - 1, gx = tx0 + xx - 1;
        float v = 0.f;
        if ((unsigned)gy < 128u && (unsigned)gx < 128u)
            v = __ldg(xb + (c << 14) + (gy << 7) + gx);
        xt[i] = v;
    }
    __syncthreads();

    const int lty = tid >> 4, lx0 = (tid & 15) << 1;
    const int pix = ((ty0 + lty) << 7) + tx0 + lx0;

    ull acc2[16];
    #pragma unroll
    for (int o = 0; o < 16; o++) acc2[o] = 0ull;

    #pragma unroll 1
    for (int g4 = 0; g4 < 4; g4++) {
        ull kk2[8];
        #pragma unroll
        for (int i = 0; i < 8; i++) kk2[i] = 0ull;

        // grouped 3x3 key conv: packed pixel-pair FMA2
        #pragma unroll 1
        for (int ci = 0; ci < 8; ci++) {
            const float* pb = xt + (g4 * 8 + ci) * CSTR + lty * XSTR + lx0;
            float pr[12];
            #pragma unroll
            for (int dy = 0; dy < 3; dy++)
                #pragma unroll
                for (int dx = 0; dx < 4; dx++)
                    pr[dy * 4 + dx] = pb[dy * XSTR + dx];
            ull pp[9];
            #pragma unroll
            for (int dy = 0; dy < 3; dy++)
                #pragma unroll
                for (int dx = 0; dx < 3; dx++)
                    pp[dy * 3 + dx] = pk2(pr[dy * 4 + dx], pr[dy * 4 + dx + 1]);
            const float* wb = sm + WK + (g4 * 64 + ci) * 12;
            #pragma unroll
            for (int oc = 0; oc < 8; oc++) {
                const float4* w4 = (const float4*)(wb + oc * 96);
                float4 wa = w4[0], wc = w4[1];
                float w8 = wb[oc * 96 + 8];
                ull k = kk2[oc];
                k = f2fma(pp[0], dup2(wa.x), k);
                k = f2fma(pp[1], dup2(wa.y), k);
                k = f2fma(pp[2], dup2(wa.z), k);
                k = f2fma(pp[3], dup2(wa.w), k);
                k = f2fma(pp[4], dup2(wc.x), k);
                k = f2fma(pp[5], dup2(wc.y), k);
                k = f2fma(pp[6], dup2(wc.z), k);
                k = f2fma(pp[7], dup2(wc.w), k);
                k = f2fma(pp[8], dup2(w8), k);
                kk2[oc] = k;
            }
        }
        // e1 contributions (x, relu(k))
        #pragma unroll 1
        for (int ci = 0; ci < 8; ci++) {
            const float* ctr = xt + (g4 * 8 + ci) * CSTR + (lty + 1) * XSTR + lx0 + 1;
            ull xc2 = pk2(ctr[0], ctr[1]);
            ull kv2 = f2relu(kk2[ci]);
            const float2* w1 = (const float2*)(sm + WE1 + ((g4 * 8 + ci) << 5));
            #pragma unroll
            for (int o = 0; o < 16; o++) {
                float2 w = w1[o];
                acc2[o] = f2fma(xc2, dup2(w.x), f2fma(kv2, dup2(w.y), acc2[o]));
            }
        }
    }
    #pragma unroll
    for (int o = 0; o < 16; o++) acc2[o] = f2relu(acc2[o]);

    // e2 + GN partials + wraw store
    float lsum[4], lsq[4];
    #pragma unroll
    for (int g4 = 0; g4 < 4; g4++) {
        ull s2 = 0ull, q2 = 0ull;
        #pragma unroll
        for (int j = 0; j < 9; j++) {
            const int o2l = g4 * 9 + j;
            const float4* w2 = (const float4*)(sm + WE2 + o2l * 16);
            ull a2 = dup2(sm[BE2 + o2l]);
            #pragma unroll
            for (int qq = 0; qq < 4; qq++) {
                float4 w = w2[qq];
                a2 = f2fma(acc2[qq * 4 + 0], dup2(w.x), a2);
                a2 = f2fma(acc2[qq * 4 + 1], dup2(w.y), a2);
                a2 = f2fma(acc2[qq * 4 + 2], dup2(w.z), a2);
                a2 = f2fma(acc2[qq * 4 + 3], dup2(w.w), a2);
            }
            *(ull*)(g_wraw + (((size_t)b * 72 + half * 36 + o2l) << 14) + pix) = a2;
            s2 = f2add(s2, a2);
            q2 = f2fma(a2, a2, q2);
        }
        float slo, shi, qlo, qhi;
        upk2(s2, slo, shi); upk2(q2, qlo, qhi);
        lsum[g4] = slo + shi; lsq[g4] = qlo + qhi;
    }

    // xv = grouped conv1x1 (this half's group)
    {
        ull xin2[32];
        #pragma unroll
        for (int ic = 0; ic < 32; ic++) {
            const float* ctr = xt + ic * CSTR + (lty + 1) * XSTR + lx0 + 1;
            xin2[ic] = pk2(ctr[0], ctr[1]);
        }
        #pragma unroll 1
        for (int ocb = 0; ocb < 4; ocb++) {
            ull a2[8];
            #pragma unroll
            for (int i = 0; i < 8; i++) a2[i] = 0ull;
            #pragma unroll
            for (int oc8 = 0; oc8 < 8; oc8++) {
                const float4* w = (const float4*)(sm + WC1 + (ocb * 8 + oc8) * 32);
                #pragma unroll
                for (int qq = 0; qq < 8; qq++) {
                    float4 wv = w[qq];
                    a2[oc8] = f2fma(xin2[qq * 4 + 0], dup2(wv.x), a2[oc8]);
                    a2[oc8] = f2fma(xin2[qq * 4 + 1], dup2(wv.y), a2[oc8]);
                    a2[oc8] = f2fma(xin2[qq * 4 + 2], dup2(wv.z), a2[oc8]);
                    a2[oc8] = f2fma(xin2[qq * 4 + 3], dup2(wv.w), a2[oc8]);
                }
            }
            #pragma unroll
            for (int oc8 = 0; oc8 < 8; oc8++)
                *(ull*)(g_xv + (((size_t)b * 64 + half * 32 + ocb * 8 + oc8) << 14) + pix) =
                    a2[oc8];
        }
    }

    // GN partial reduce
    __syncthreads();
    #pragma unroll
    for (int off = 16; off; off >>= 1)
        #pragma unroll
        for (int g4 = 0; g4 < 4; g4++) {
            lsum[g4] += __shfl_xor_sync(0xffffffffu, lsum[g4], off);
            lsq[g4]  += __shfl_xor_sync(0xffffffffu, lsq[g4],  off);
        }
    const int wid = tid >> 5, lane = tid & 31;
    if (lane == 0) {
        #pragma unroll
        for (int g4 = 0; g4 < 4; g4++) {
            sm[wid * 8 + g4] = lsum[g4];
            sm[wid * 8 + 4 + g4] = lsq[g4];
        }
    }
    __syncthreads();
    if (tid < 8) {
        float s = 0.f;
        #pragma unroll
        for (int w = 0; w < 8; w++) s += sm[w * 8 + tid];
        int slot = (b * 32 + blockIdx.y * 4 + blockIdx.x) * 16;
        int e = (tid < 4) ? (half * 4 + tid) : (8 + half * 4 + tid - 4);
        g_gnpart[slot + e] = s;
    }
}

// ---------------- GN stats (parallel) ----------------------------------------
__global__ void statsK()
{
    int tid = threadIdx.x;
    int idx = tid >> 3, k = tid & 7;
    int b = idx >> 3, gg = idx & 7;
    float s = 0.f, q = 0.f;
    #pragma unroll
    for (int t = 0; t < 4; t++) {
        int tile = k * 4 + t;
        s += g_gnpart[(b * 32 + tile) * 16 + gg];
        q += g_gnpart[(b * 32 + tile) * 16 + 8 + gg];
    }
    #pragma unroll
    for (int off = 4; off; off >>= 1) {
        s += __shfl_xor_sync(0xffffffffu, s, off);
        q += __shfl_xor_sync(0xffffffffu, q, off);
    }
    if (k == 0) {
        const float inv_n = 1.f / 147456.f;
        float m = s * inv_n;
        float v = fmaf(q, inv_n, -m * m);
        g_gnstat[idx * 2] = m;
        g_gnstat[idx * 2 + 1] = rsqrtf(v + 1e-5f);
    }
}

// ---------------- passB (half-split, FMA2) -------------------------------------
#define ST  0
#define SC  8
#define XTB 264
#define SMEMB ((XTB + XT_SZ_H) * 4)

__global__ void __launch_bounds__(256, 2) passB(float* __restrict__ out)
{
    extern __shared__ float sm[];
    const int tid = threadIdx.x;
    const int b = blockIdx.z >> 1, half = blockIdx.z & 1;
    const int ty0 = blockIdx.y * TILE_H, tx0 = blockIdx.x * TILE_W;

    if (tid < 8) sm[ST + tid] = g_gnstat[b * 16 + half * 8 + tid];
    if (tid < 256) sm[SC + tid] = 0.f;

    float* xt = sm + XTB;
    const float* xvb = g_xv + (size_t)b * 64 * HW + ((size_t)half << 19);
    for (int i = tid; i < XT_SZ_H; i += 256) {
        int c = i / CSTR, r = i - c * CSTR, yy = r / XSTR, xx = r - yy * XSTR;
        int gy = ty0 + yy - 1, gx = tx0 + xx - 1;
        float v = 0.f;
        if ((unsigned)gy < 128u && (unsigned)gx < 128u)
            v = __ldg(xvb + (c << 14) + (gy << 7) + gx);
        xt[i] = v;
    }
    __syncthreads();

    const int lty = tid >> 4, lx0 = (tid & 15) << 1;
    const int pix = ((ty0 + lty) << 7) + tx0 + lx0;
    const int wid = tid >> 5;

    #pragma unroll
    for (int g4 = 0; g4 < 4; g4++) {
        float mean = sm[ST + g4 * 2], rstd = sm[ST + g4 * 2 + 1];
        ull bw[9];
        #pragma unroll
        for (int t = 0; t < 9; t++) {
            int o2 = half * 36 + g4 * 9 + t;
            float2 raw = *(const float2*)(g_wraw + (((size_t)b * 72 + o2) << 14) + pix);
            float w0 = fmaf((raw.x - mean) * rstd, c_gnw[o2], c_gnb[o2]);
            float w1 = fmaf((raw.y - mean) * rstd, c_gnw[o2], c_gnb[o2]);
            bw[t] = pk2(w0, w1);
        }
        #pragma unroll 1
        for (int cc = 0; cc < 8; cc++) {
            int cl = g4 * 8 + cc;
            const float* pb = xt + cl * CSTR + lty * XSTR + lx0;
            ull a2 = 0ull;
            #pragma unroll
            for (int dy = 0; dy < 3; dy++) {
                float r0 = pb[dy * XSTR], r1 = pb[dy * XSTR + 1];
                float r2 = pb[dy * XSTR + 2], r3 = pb[dy * XSTR + 3];
                a2 = f2fma(pk2(r0, r1), bw[dy * 3 + 0], a2);
                a2 = f2fma(pk2(r1, r2), bw[dy * 3 + 1], a2);
                a2 = f2fma(pk2(r2, r3), bw[dy * 3 + 2], a2);
            }
            *(ull*)(out + (((size_t)b * 64 + half * 32 + cl) << 14) + pix) = a2;
            float a0, a1; upk2(a2, a0, a1);
            float s = a0 + a1;
            #pragma unroll
            for (int off = 16; off; off >>= 1)
                s += __shfl_xor_sync(0xffffffffu, s, off);
            if ((tid & 31) == 0) sm[SC + wid * 32 + cl] += s;
        }
    }
    __syncthreads();
    if (tid < 32) {
        float s = 0.f;
        #pragma unroll
        for (int w = 0; w < 8; w++) s += sm[SC + w * 32 + tid];
        g_chanpart[(b * 32 + blockIdx.y * 4 + blockIdx.x) * 64 + half * 32 + tid] = s;
    }
}

// ---------------- attention -----------------------------------------------------
__global__ void attnK()
{
    int b = blockIdx.x, tid = threadIdx.x;
    int c = tid >> 3, k = tid & 7;
    __shared__ float m[64], t4[4];
    float s = 0.f;
    #pragma unroll
    for (int t = 0; t < 4; t++)
        s += g_chanpart[(b * 32 + k * 4 + t) * 64 + c];
    #pragma unroll
    for (int off = 4; off; off >>= 1)
        s += __shfl_xor_sync(0xffffffffu, s, off);
    if (k == 0) m[c] = s * (1.f / 16384.f);
    __syncthreads();
    if (tid < 4) {
        float a = 0.f;
        for (int i = 0; i < 64; i++) a = fmaf(m[i], c_wdu1[tid * 64 + i], a);
        t4[tid] = fmaxf(a, 0.f);
    }
    __syncthreads();
    if (tid < 64) {
        float a = 0.f;
        #pragma unroll
        for (int j = 0; j < 4; j++) a = fmaf(t4[j], c_wdu2[tid * 4 + j], a);
        g_yscale[b * 64 + tid] = 1.f / (1.f + expf(-a));
    }
}

// ---------------- final scale -----------------------------------------------------
__global__ void scaleK(float* __restrict__ out)
{
    int i = blockIdx.x * blockDim.x + threadIdx.x;
    float4* p = (float4*)out;
    float s = g_yscale[i >> 12];
    float4 v = p[i];
    v.x *= s; v.y *= s; v.z *= s; v.w *= s;
    p[i] = v;
}

// ---------------- launcher ---------------------------------------------------------
extern "C" void kernel_launch(void* const* d_in, const int* in_sizes, int n_in,
                              void* d_out, int out_size)
{
    const float* x    = (const float*)d_in[0];
    const float* wkey = (const float*)d_in[1];
    const float* we1  = (const float*)d_in[2];
    const float* we2  = (const float*)d_in[3];
    const float* be2  = (const float*)d_in[4];
    const float* gnw  = (const float*)d_in[5];
    const float* gnb  = (const float*)d_in[6];
    const float* wc1  = (const float*)d_in[7];
    const float* wdu1 = (const float*)d_in[8];
    const float* wdu2 = (const float*)d_in[9];
    float* out = (float*)d_out;

    cudaMemcpyToSymbolAsync(c_gnw,  gnw,  72 * 4,  0, cudaMemcpyDeviceToDevice, 0);
    cudaMemcpyToSymbolAsync(c_gnb,  gnb,  72 * 4,  0, cudaMemcpyDeviceToDevice, 0);
    cudaMemcpyToSymbolAsync(c_wdu1, wdu1, 256 * 4, 0, cudaMemcpyDeviceToDevice, 0);
    cudaMemcpyToSymbolAsync(c_wdu2, wdu2, 256 * 4, 0, cudaMemcpyDeviceToDevice, 0);

    cudaFuncSetAttribute(passA, cudaFuncAttributeMaxDynamicSharedMemorySize, SMEMA);
    cudaFuncSetAttribute(passB, cudaFuncAttributeMaxDynamicSharedMemorySize, SMEMB);

    dim3 grid(4, 8, 16);
    passA<<<grid, 256, SMEMA>>>(x, wkey, we1, we2, be2, wc1);
    statsK<<<1, 512>>>();
    passB<<<grid, 256, SMEMB>>>(out);
    attnK<<<8, 512>>>();
    scaleK<<<8192, 256>>>(out);
}